// round 16
// baseline (speedup 1.0000x reference)
#include <cuda_runtime.h>
#include <cuda_fp16.h>
#include <math.h>
#include <stdint.h>

// ---------------------------------------------------------------------------
// GeometricAttentionLayer on GB300 — fp16 mma.sync + ldmatrix engine v6r3
//   R15 configuration (best 1303.4us) + load/compute interleave in gemm_h3:
//   each split term's fragments load under the previous term's MMA sweep.
//   Per-accumulator term order unchanged -> bit-identical results.
//   3-pass split GEMMs (qk-proj, scores): 256x128, 64x64 warp, 2-stage.
//   Single-pass GEMMs (v-proj, attn@V, out-proj): 128x128, 3-stage, 2 CTA/SM.
// ---------------------------------------------------------------------------

#define BM 256
#define BN 128
#define BK 64
#define ATILE 32768                       // 256 rows x 128 B
#define BTILE 16384                       // 128 rows x 128 B
#define ST3 (2 * ATILE + 2 * BTILE)       // 96 KB / stage
#define SMEM_3 (2 * ST3)                  // 192 KB
#define ST1 (2 * BTILE)                   // 32 KB / stage (h1: 128x128)
#define SMEM_1 (3 * ST1)                  // 96 KB

__constant__ int c_ip[8] = {0, 2, 3, 4, 8, 9, 10, 14};

// ------------------------- scratch (device globals) ------------------------
__device__ __align__(1024) __half g_xh  [4096LL * 1024];
__device__ __align__(1024) __half g_xl  [4096LL * 1024];
__device__ __align__(1024) __half g_Wqkh[4608 * 1024];
__device__ __align__(1024) __half g_Wqkl[4608 * 1024];
__device__ __align__(1024) __half g_Wvh [1024 * 1024];
__device__ __align__(1024) __half g_Woh [1024 * 8192];
__device__ __align__(1024) __half g_qkmh[4096LL * 4608];
__device__ __align__(1024) __half g_qkml[4096LL * 4608];
__device__ __align__(1024) __half g_vT  [1024LL * 4096];
__device__ __align__(1024) float  g_sc  [16LL * 2048 * 2048];
__device__ __align__(1024) __half g_pr  [16LL * 2048 * 2048];
__device__ __align__(1024) __half g_ao  [4096LL * 8192];

// ------------------------------ helpers ------------------------------------
__device__ __forceinline__ uint32_t smem_u32(const void* p) {
    uint32_t a;
    asm("{ .reg .u64 t; cvta.to.shared.u64 t, %1; cvt.u32.u64 %0, t; }" : "=r"(a) : "l"(p));
    return a;
}

__device__ __forceinline__ void cp16(uint32_t dst, const __half* src) {
    asm volatile("cp.async.cg.shared.global [%0], [%1], 16;"
                 :: "r"(dst), "l"(src) : "memory");
}

#define LDSM_X4(r0, r1, r2, r3, addr)                                         \
    asm volatile("ldmatrix.sync.aligned.m8n8.x4.shared.b16 {%0,%1,%2,%3}, [%4];" \
        : "=r"(r0), "=r"(r1), "=r"(r2), "=r"(r3) : "r"(addr))

#define MMA_F16(acc, a, b)                                                    \
    asm volatile(                                                             \
        "mma.sync.aligned.m16n8k16.row.col.f32.f16.f16.f32 "                  \
        "{%0,%1,%2,%3}, {%4,%5,%6,%7}, {%8,%9}, {%0,%1,%2,%3};"               \
        : "+f"((acc)[0]), "+f"((acc)[1]), "+f"((acc)[2]), "+f"((acc)[3])      \
        : "r"((a)[0]), "r"((a)[1]), "r"((a)[2]), "r"((a)[3]),                 \
          "r"((b)[0]), "r"((b)[1]))

// ------------------- weight precompute (smem blade, 16 out/thread) ---------
__global__ __launch_bounds__(256) void make_weightT2(
    const float* __restrict__ w, const float* __restrict__ blade,
    __half* __restrict__ Wh, __half* __restrict__ Wl,
    int I, int mode, float scale, long long totalThreads, int storeLo)
{
    __shared__ float bl[9 * 256];
    for (int idx = threadIdx.x; idx < 9 * 256; idx += 256)
        bl[idx] = blade[idx];
    __syncthreads();

    long long t = (long long)blockIdx.x * 256 + threadIdx.x;
    if (t >= totalThreads) return;
    int col = (int)(t / I);
    int i   = (int)(t % I);

    int j, y;
    if (mode == 0)      { j = col >> 4; y = col & 15; }
    else if (mode == 1) { int e = col & 7; int d = (col >> 3) & 63; int h = col >> 9;
                          j = d * 8 + h; y = c_ip[e]; }
    else                { int e = col & 7; j = col >> 3; y = c_ip[e]; }

    float wr[9];
    const float* wp = w + ((long long)j * I + i) * 9;
    #pragma unroll
    for (int b = 0; b < 9; b++) wr[b] = wp[b];

    __half2 hv[8], lv[8];
    #pragma unroll
    for (int xc2 = 0; xc2 < 8; xc2++) {
        float s0 = 0.f, s1 = 0.f;
        #pragma unroll
        for (int b = 0; b < 9; b++) {
            s0 += wr[b] * bl[b * 256 + (xc2 * 2 + 0) * 16 + y];
            s1 += wr[b] * bl[b * 256 + (xc2 * 2 + 1) * 16 + y];
        }
        s0 *= scale; s1 *= scale;
        __half h0 = __float2half_rn(s0), h1 = __float2half_rn(s1);
        hv[xc2] = __halves2half2(h0, h1);
        lv[xc2] = __halves2half2(__float2half_rn(s0 - __half2float(h0)),
                                 __float2half_rn(s1 - __half2float(h1)));
    }

    long long base = (long long)col * (I * 16) + i * 16;
    __half2* oh = reinterpret_cast<__half2*>(Wh + base);
    #pragma unroll
    for (int u = 0; u < 8; u++) oh[u] = hv[u];
    if (storeLo) {
        __half2* ol = reinterpret_cast<__half2*>(Wl + base);
        #pragma unroll
        for (int u = 0; u < 8; u++) ol[u] = lv[u];
    }
}

// ------------------------------ fp16 split pass ----------------------------
__global__ void split_f16(const float4* __restrict__ in,
                          __half2* __restrict__ oh, __half2* __restrict__ ol, int n4)
{
    int i = blockIdx.x * 256 + threadIdx.x;
    if (i >= n4) return;
    float4 v = in[i];
    __half hx = __float2half_rn(v.x), hy = __float2half_rn(v.y);
    __half hz = __float2half_rn(v.z), hw = __float2half_rn(v.w);
    oh[i * 2 + 0] = __halves2half2(hx, hy);
    oh[i * 2 + 1] = __halves2half2(hz, hw);
    ol[i * 2 + 0] = __halves2half2(__float2half_rn(v.x - __half2float(hx)),
                                   __float2half_rn(v.y - __half2float(hy)));
    ol[i * 2 + 1] = __halves2half2(__float2half_rn(v.z - __half2float(hz)),
                                   __float2half_rn(v.w - __half2float(hw)));
}

// ------------------ single fp16 GEMM (NT), 128x128 tile --------------------
__global__ __launch_bounds__(256, 2) void gemm_h1(
    const __half* __restrict__ Ag, const __half* __restrict__ Bg,
    float* __restrict__ Cf, __half* __restrict__ Chh,
    int K, int lda, int ldb, int ldc,
    long long aB, long long aH, long long bB, long long bH,
    long long cB, long long cH, int nH, int halfout)
{
    extern __shared__ char sm[];
    const uint32_t smb = smem_u32(sm);

    const int tid = threadIdx.x;
    const int bb = blockIdx.z / nH, hh = blockIdx.z - bb * nH;
    const __half* A = Ag + bb * aB + hh * aH + (long long)(blockIdx.y * 128) * lda;
    const __half* B = Bg + bb * bB + hh * bH + (long long)(blockIdx.x * 128) * ldb;

    const int ldrow = tid >> 3;
    const int seg   = tid & 7;
    const uint32_t swoff = (uint32_t)((seg ^ (ldrow & 7)) << 4);
    uint32_t stoff[4];
    #pragma unroll
    for (int i = 0; i < 4; i++) stoff[i] = (uint32_t)((ldrow + 32 * i) * 128) + swoff;

#define ISSUE1(ch, slot) do {                                                 \
        const __half* _a = A + (long long)(ch) * BK + (seg << 3);             \
        uint32_t _da = smb + (uint32_t)(slot) * ST1;                          \
        _Pragma("unroll")                                                     \
        for (int _i = 0; _i < 4; _i++)                                        \
            cp16(_da + stoff[_i], _a + (long long)(ldrow + 32 * _i) * lda);   \
        const __half* _b = B + (long long)(ch) * BK + (seg << 3);             \
        uint32_t _db = smb + (uint32_t)(slot) * ST1 + BTILE;                  \
        _Pragma("unroll")                                                     \
        for (int _i = 0; _i < 4; _i++)                                        \
            cp16(_db + stoff[_i], _b + (long long)(ldrow + 32 * _i) * ldb);   \
    } while (0)

    const int lane = tid & 31;
    const int wm = ((tid >> 5) & 1) * 64;
    const int wn = (tid >> 6) * 32;
    const int qr = lane >> 2;
    const int qc = lane & 3;
    const int l7 = lane & 7;
    const uint32_t aRow = (uint32_t)(wm + (lane & 15)) * 128;
    const int aCb = lane >> 4;
    const uint32_t bRow = (uint32_t)(wn + l7 + ((lane >> 4) << 3)) * 128;
    const int bCb = (lane >> 3) & 1;

    float acc[4][4][4];
    #pragma unroll
    for (int mi = 0; mi < 4; mi++)
        #pragma unroll
        for (int ni = 0; ni < 4; ni++)
            #pragma unroll
            for (int q = 0; q < 4; q++) acc[mi][ni][q] = 0.f;

    const int nch = K >> 6;

    #pragma unroll
    for (int p = 0; p < 2; p++) {
        if (p < nch) ISSUE1(p, p);
        asm volatile("cp.async.commit_group;" ::: "memory");
    }

    for (int ch = 0; ch < nch; ch++) {
        asm volatile("cp.async.wait_group 1;" ::: "memory");
        __syncthreads();

        int pf = ch + 2;
        if (pf < nch) ISSUE1(pf, pf % 3);
        asm volatile("cp.async.commit_group;" ::: "memory");

        const int slot = ch % 3;
        const uint32_t tA = smb + slot * ST1 + aRow;
        const uint32_t tB = smb + slot * ST1 + BTILE + bRow;

        #pragma unroll
        for (int kk = 0; kk < 4; kk++) {
            const uint32_t aC = (uint32_t)((((kk << 1) + aCb) ^ l7) << 4);
            const uint32_t bC = (uint32_t)((((kk << 1) + bCb) ^ l7) << 4);
            uint32_t a[4][4], b[4][2];
            #pragma unroll
            for (int mi = 0; mi < 4; mi++)
                LDSM_X4(a[mi][0], a[mi][1], a[mi][2], a[mi][3], tA + mi * 2048 + aC);
            #pragma unroll
            for (int g = 0; g < 2; g++)
                LDSM_X4(b[2*g][0], b[2*g][1], b[2*g+1][0], b[2*g+1][1], tB + g * 2048 + bC);
            #pragma unroll
            for (int mi = 0; mi < 4; mi++)
                #pragma unroll
                for (int ni = 0; ni < 4; ni++)
                    MMA_F16(acc[mi][ni], a[mi], b[ni]);
        }
    }
#undef ISSUE1

    const long long cOff = bb * cB + hh * cH;
    const int rbase = blockIdx.y * 128 + wm + qr;
    const int cbase = blockIdx.x * 128 + wn + (qc << 1);
    #pragma unroll
    for (int mi = 0; mi < 4; mi++) {
        #pragma unroll
        for (int ni = 0; ni < 4; ni++) {
            const long long r = rbase + mi * 16;
            const int c = cbase + ni * 8;
            if (halfout) {
                __half* cb = Chh + cOff;
                *reinterpret_cast<__half2*>(&cb[r * ldc + c]) =
                    __halves2half2(__float2half_rn(acc[mi][ni][0]),
                                   __float2half_rn(acc[mi][ni][1]));
                *reinterpret_cast<__half2*>(&cb[(r + 8) * ldc + c]) =
                    __halves2half2(__float2half_rn(acc[mi][ni][2]),
                                   __float2half_rn(acc[mi][ni][3]));
            } else {
                float* cb = Cf + cOff;
                *reinterpret_cast<float2*>(&cb[r * ldc + c]) =
                    make_float2(acc[mi][ni][0], acc[mi][ni][1]);
                *reinterpret_cast<float2*>(&cb[(r + 8) * ldc + c]) =
                    make_float2(acc[mi][ni][2], acc[mi][ni][3]);
            }
        }
    }
}

// ------------------ 3-term fp16 split GEMM (NT), 256x128 tile --------------
// acc += Ahi*Bhi + Ahi*Blo + Alo*Bhi, term-major with loads interleaved under
// the previous term's MMA sweep (per-acc order unchanged -> bit-identical).
__global__ __launch_bounds__(256, 1) void gemm_h3(
    const __half* __restrict__ Ah, const __half* __restrict__ Al,
    const __half* __restrict__ Bh, const __half* __restrict__ Bl,
    float* __restrict__ Cf, __half* __restrict__ Chh, __half* __restrict__ Chl,
    int K, int lda, int ldb, int ldc,
    long long aB, long long aH, long long bB, long long bH,
    long long cB, long long cH, int nH, int outmode)
{
    extern __shared__ char sm[];
    const uint32_t smb = smem_u32(sm);

    const int tid = threadIdx.x;
    const int bb = blockIdx.z / nH, hh = blockIdx.z - bb * nH;
    const long long aOff = bb * aB + hh * aH + (long long)(blockIdx.y * BM) * lda;
    const long long bOff = bb * bB + hh * bH + (long long)(blockIdx.x * BN) * ldb;
    const __half* pAh = Ah + aOff;
    const __half* pAl = Al + aOff;
    const __half* pBh = Bh + bOff;
    const __half* pBl = Bl + bOff;

    const int ldrow = tid >> 3;
    const int seg   = tid & 7;
    const uint32_t swoff = (uint32_t)((seg ^ (ldrow & 7)) << 4);

#define ISSUE3(ch, slot) do {                                                 \
        uint32_t _sb = smb + (uint32_t)(slot) * ST3;                          \
        const __half* _s0 = pAh + (long long)(ch) * BK + (seg << 3);          \
        const __half* _s1 = pAl + (long long)(ch) * BK + (seg << 3);          \
        _Pragma("unroll")                                                     \
        for (int _i = 0; _i < 8; _i++) {                                      \
            uint32_t _o = (uint32_t)((ldrow + 32 * _i) * 128) + swoff;        \
            long long _g = (long long)(ldrow + 32 * _i) * lda;                \
            cp16(_sb + _o, _s0 + _g);                                         \
            cp16(_sb + ATILE + _o, _s1 + _g);                                 \
        }                                                                     \
        const __half* _s2 = pBh + (long long)(ch) * BK + (seg << 3);          \
        const __half* _s3 = pBl + (long long)(ch) * BK + (seg << 3);          \
        _Pragma("unroll")                                                     \
        for (int _i = 0; _i < 4; _i++) {                                      \
            uint32_t _o = (uint32_t)((ldrow + 32 * _i) * 128) + swoff;        \
            long long _g = (long long)(ldrow + 32 * _i) * ldb;                \
            cp16(_sb + 2 * ATILE + _o, _s2 + _g);                             \
            cp16(_sb + 2 * ATILE + BTILE + _o, _s3 + _g);                     \
        }                                                                     \
    } while (0)

    const int lane = tid & 31;
    const int wid = tid >> 5;
    const int wm = (wid & 3) * 64;
    const int wn = (wid >> 2) * 64;
    const int qr = lane >> 2;
    const int qc = lane & 3;
    const int l7 = lane & 7;
    const uint32_t aRow = (uint32_t)(wm + (lane & 15)) * 128;
    const int aCb = lane >> 4;
    const uint32_t bRow = (uint32_t)(wn + l7 + ((lane >> 4) << 3)) * 128;
    const int bCb = (lane >> 3) & 1;

    float acc[4][8][4];
    #pragma unroll
    for (int mi = 0; mi < 4; mi++)
        #pragma unroll
        for (int ni = 0; ni < 8; ni++)
            #pragma unroll
            for (int q = 0; q < 4; q++) acc[mi][ni][q] = 0.f;

    const int nch = K >> 6;

    ISSUE3(0, 0);
    asm volatile("cp.async.commit_group;" ::: "memory");

    for (int ch = 0; ch < nch; ch++) {
        asm volatile("cp.async.wait_group 0;" ::: "memory");
        __syncthreads();
        if (ch + 1 < nch) {
            ISSUE3(ch + 1, (ch + 1) & 1);
            asm volatile("cp.async.commit_group;" ::: "memory");
        }

        const int slot = ch & 1;
        const uint32_t tAh = smb + slot * ST3 + aRow;
        const uint32_t tAl = smb + slot * ST3 + ATILE + aRow;
        const uint32_t tBh = smb + slot * ST3 + 2 * ATILE + bRow;
        const uint32_t tBl = smb + slot * ST3 + 2 * ATILE + BTILE + bRow;

        #pragma unroll
        for (int kk = 0; kk < 4; kk++) {
            const uint32_t aC = (uint32_t)((((kk << 1) + aCb) ^ l7) << 4);
            const uint32_t bC = (uint32_t)((((kk << 1) + bCb) ^ l7) << 4);
            uint32_t ah[4][4], al[4][4], bh[8][2], bl[8][2];

            // term 1 fragments: ah, bl
            #pragma unroll
            for (int mi = 0; mi < 4; mi++)
                LDSM_X4(ah[mi][0], ah[mi][1], ah[mi][2], ah[mi][3], tAh + mi * 2048 + aC);
            #pragma unroll
            for (int g = 0; g < 4; g++)
                LDSM_X4(bl[2*g][0], bl[2*g][1], bl[2*g+1][0], bl[2*g+1][1], tBl + g * 2048 + bC);

            // sweep 1 (ah*bl); bh loads hide under it
            #pragma unroll
            for (int g = 0; g < 4; g++)
                LDSM_X4(bh[2*g][0], bh[2*g][1], bh[2*g+1][0], bh[2*g+1][1], tBh + g * 2048 + bC);
            #pragma unroll
            for (int mi = 0; mi < 4; mi++)
                #pragma unroll
                for (int ni = 0; ni < 8; ni++)
                    MMA_F16(acc[mi][ni], ah[mi], bl[ni]);

            // al loads hide under tail of sweep 1
            #pragma unroll
            for (int mi = 0; mi < 4; mi++)
                LDSM_X4(al[mi][0], al[mi][1], al[mi][2], al[mi][3], tAl + mi * 2048 + aC);

            // sweep 2 (al*bh)
            #pragma unroll
            for (int mi = 0; mi < 4; mi++)
                #pragma unroll
                for (int ni = 0; ni < 8; ni++)
                    MMA_F16(acc[mi][ni], al[mi], bh[ni]);

            // sweep 3 (ah*bh)
            #pragma unroll
            for (int mi = 0; mi < 4; mi++)
                #pragma unroll
                for (int ni = 0; ni < 8; ni++)
                    MMA_F16(acc[mi][ni], ah[mi], bh[ni]);
        }
    }
#undef ISSUE3

    const long long cOff = bb * cB + hh * cH;
    const int rbase = blockIdx.y * BM + wm + qr;
    const int cbase = blockIdx.x * BN + wn + (qc << 1);
    #pragma unroll
    for (int mi = 0; mi < 4; mi++) {
        #pragma unroll
        for (int ni = 0; ni < 8; ni++) {
            const long long r = rbase + mi * 16;
            const int c = cbase + ni * 8;
            float v[4] = {acc[mi][ni][0], acc[mi][ni][1], acc[mi][ni][2], acc[mi][ni][3]};
            if (outmode == 2) {
                __half h0 = __float2half_rn(v[0]), h1 = __float2half_rn(v[1]);
                __half h2 = __float2half_rn(v[2]), h3 = __float2half_rn(v[3]);
                __half* ch_ = Chh + cOff;
                __half* cl_ = Chl + cOff;
                *reinterpret_cast<__half2*>(&ch_[r * ldc + c])       = __halves2half2(h0, h1);
                *reinterpret_cast<__half2*>(&ch_[(r + 8) * ldc + c]) = __halves2half2(h2, h3);
                *reinterpret_cast<__half2*>(&cl_[r * ldc + c]) =
                    __halves2half2(__float2half_rn(v[0] - __half2float(h0)),
                                   __float2half_rn(v[1] - __half2float(h1)));
                *reinterpret_cast<__half2*>(&cl_[(r + 8) * ldc + c]) =
                    __halves2half2(__float2half_rn(v[2] - __half2float(h2)),
                                   __float2half_rn(v[3] - __half2float(h3)));
            } else {
                float* cb = Cf + cOff;
                __stcs(reinterpret_cast<float2*>(&cb[r * ldc + c]),
                       make_float2(v[0], v[1]));
                __stcs(reinterpret_cast<float2*>(&cb[(r + 8) * ldc + c]),
                       make_float2(v[2], v[3]));
            }
        }
    }
}

// ------------------------- softmax (2048 cols, fp32 -> half) ---------------
__global__ __launch_bounds__(256) void softmax2048(const float* __restrict__ sc,
                                                   __half* __restrict__ pr)
{
    __shared__ float red[8];
    const float4* p = reinterpret_cast<const float4*>(sc + (long long)blockIdx.x * 2048);
    __half2* q = reinterpret_cast<__half2*>(pr + (long long)blockIdx.x * 2048);
    const int t = threadIdx.x;
    const int wid = t >> 5, lid = t & 31;

    float4 a = __ldcs(p + t);
    float4 b = __ldcs(p + t + 256);

    float mx = fmaxf(fmaxf(fmaxf(a.x, a.y), fmaxf(a.z, a.w)),
                     fmaxf(fmaxf(b.x, b.y), fmaxf(b.z, b.w)));
    #pragma unroll
    for (int s = 16; s > 0; s >>= 1) mx = fmaxf(mx, __shfl_xor_sync(0xffffffffu, mx, s));
    if (lid == 0) red[wid] = mx;
    __syncthreads();
    if (t < 32) {
        float m = (t < 8) ? red[t] : -INFINITY;
        #pragma unroll
        for (int s = 4; s > 0; s >>= 1) m = fmaxf(m, __shfl_xor_sync(0xffffffffu, m, s));
        if (t == 0) red[0] = m;
    }
    __syncthreads();
    mx = red[0];
    __syncthreads();

    a.x = __expf(a.x - mx); a.y = __expf(a.y - mx); a.z = __expf(a.z - mx); a.w = __expf(a.w - mx);
    b.x = __expf(b.x - mx); b.y = __expf(b.y - mx); b.z = __expf(b.z - mx); b.w = __expf(b.w - mx);
    float sum = a.x + a.y + a.z + a.w + b.x + b.y + b.z + b.w;
    #pragma unroll
    for (int s = 16; s > 0; s >>= 1) sum += __shfl_xor_sync(0xffffffffu, sum, s);
    if (lid == 0) red[wid] = sum;
    __syncthreads();
    if (t < 32) {
        float m = (t < 8) ? red[t] : 0.f;
        #pragma unroll
        for (int s = 4; s > 0; s >>= 1) m += __shfl_xor_sync(0xffffffffu, m, s);
        if (t == 0) red[0] = m;
    }
    __syncthreads();
    float inv = 1.0f / red[0];

    __half2 q0 = __halves2half2(__float2half_rn(a.x * inv), __float2half_rn(a.y * inv));
    __half2 q1 = __halves2half2(__float2half_rn(a.z * inv), __float2half_rn(a.w * inv));
    __half2 q2 = __halves2half2(__float2half_rn(b.x * inv), __float2half_rn(b.y * inv));
    __half2 q3 = __halves2half2(__float2half_rn(b.z * inv), __float2half_rn(b.w * inv));
    uint2 u01 = make_uint2(*reinterpret_cast<uint32_t*>(&q0), *reinterpret_cast<uint32_t*>(&q1));
    uint2 u23 = make_uint2(*reinterpret_cast<uint32_t*>(&q2), *reinterpret_cast<uint32_t*>(&q3));
    __stcs(reinterpret_cast<uint2*>(q + t * 2), u01);
    __stcs(reinterpret_cast<uint2*>(q + (t + 256) * 2), u23);
}

// ------------------------------ host side ----------------------------------
template <typename T>
static T* sym_addr(const void* symbol)
{
    void* p = nullptr;
    cudaGetSymbolAddress(&p, symbol);
    return (T*)p;
}

extern "C" void kernel_launch(void* const* d_in, const int* in_sizes, int n_in,
                              void* d_out, int out_size)
{
    const float* x     = (const float*)d_in[0];
    const float* blade = (const float*)d_in[1];
    const float* w_q   = (const float*)d_in[2];
    const float* w_k   = (const float*)d_in[3];
    const float* w_v   = (const float*)d_in[4];
    const float* w_o   = (const float*)d_in[5];
    float* out = (float*)d_out;

    __half* xh   = sym_addr<__half>(g_xh),   *xl   = sym_addr<__half>(g_xl);
    __half* Wqkh = sym_addr<__half>(g_Wqkh), *Wqkl = sym_addr<__half>(g_Wqkl);
    __half* Wvh  = sym_addr<__half>(g_Wvh);
    __half* Woh  = sym_addr<__half>(g_Woh);
    __half* qkmh = sym_addr<__half>(g_qkmh), *qkml = sym_addr<__half>(g_qkml);
    __half* vT   = sym_addr<__half>(g_vT);
    float*  sc   = sym_addr<float >(g_sc);
    __half* pr   = sym_addr<__half>(g_pr);
    __half* ao   = sym_addr<__half>(g_ao);

    static cudaStream_t s1 = nullptr, s2 = nullptr;
    static cudaEvent_t eF = nullptr, e0 = nullptr, e1 = nullptr, e3 = nullptr, e4 = nullptr;
    if (s1 == nullptr) {
        cudaStreamCreateWithFlags(&s1, cudaStreamNonBlocking);
        cudaStreamCreateWithFlags(&s2, cudaStreamNonBlocking);
        cudaEventCreateWithFlags(&eF, cudaEventDisableTiming);
        cudaEventCreateWithFlags(&e0, cudaEventDisableTiming);
        cudaEventCreateWithFlags(&e1, cudaEventDisableTiming);
        cudaEventCreateWithFlags(&e3, cudaEventDisableTiming);
        cudaEventCreateWithFlags(&e4, cudaEventDisableTiming);
        cudaFuncSetAttribute(gemm_h1, cudaFuncAttributeMaxDynamicSharedMemorySize, SMEM_1);
        cudaFuncSetAttribute(gemm_h3, cudaFuncAttributeMaxDynamicSharedMemorySize, SMEM_3);
    }

    const float scale = 1.0f / sqrtf(512.0f);

    const long long xOff   = 2048LL * 1024;
    const long long qkOff  = 2048LL * 4608;
    const long long scOff  = 8LL * 2048 * 2048;
    const long long aoOff  = 2048LL * 8192;
    const long long outOff = 2048LL * 1024;

    // ---- fork ----
    cudaEventRecord(eF, 0);
    cudaStreamWaitEvent(s1, eF, 0);
    cudaStreamWaitEvent(s2, eF, 0);

    // s1: q+k weight precompute
    {
        long long tq = 4096LL * 64;
        make_weightT2<<<(unsigned)((tq + 255) / 256), 256, 0, s1>>>(
            w_q, blade, Wqkh, Wqkl, 64, 1, scale, tq, 1);
        long long tk = 512LL * 64;
        make_weightT2<<<(unsigned)((tk + 255) / 256), 256, 0, s1>>>(
            w_k, blade, Wqkh + 4096LL * 1024, Wqkl + 4096LL * 1024, 64, 2, 1.0f, tk, 1);
        cudaEventRecord(e1, s1);
    }
    // s2: v + o weight precompute
    {
        long long tv = 1024LL * 64;
        make_weightT2<<<(unsigned)((tv + 255) / 256), 256, 0, s2>>>(
            w_v, blade, Wvh, nullptr, 64, 0, 1.0f, tv, 0);
        long long to = 1024LL * 512;
        make_weightT2<<<(unsigned)((to + 255) / 256), 256, 0, s2>>>(
            w_o, blade, Woh, nullptr, 512, 0, 1.0f, to, 0);
    }

    // main: input split
    split_f16<<<4096, 256>>>((const float4*)x, (__half2*)xh, (__half2*)xl, 4096 * 1024 / 4);
    cudaEventRecord(e0, 0);

    // s2: v projection (all tokens): vT[f, m]
    cudaStreamWaitEvent(s2, e0, 0);
    gemm_h1<<<dim3(4096 / 128, 1024 / 128, 1), 256, SMEM_1, s2>>>(
        Wvh, xh, nullptr, vT, 1024, 1024, 1024, 4096,
        0, 0, 0, 0, 0, 0, 1, 1);
    cudaEventRecord(e3, s2);

    // ---- per-batch pipelines: batch 0 on stream 0, batch 1 on s1 ----
    cudaStreamWaitEvent(0, e1, 0);
    cudaStreamWaitEvent(s1, e0, 0);

    cudaStream_t bs[2] = { (cudaStream_t)0, s1 };
    for (int b = 0; b < 2; b++) {
        cudaStream_t st = bs[b];

        // qk projection (rows of batch b)
        gemm_h3<<<dim3(4608 / 128, 2048 / 256, 1), 256, SMEM_3, st>>>(
            xh + b * xOff, xl + b * xOff, Wqkh, Wqkl,
            nullptr, qkmh + b * qkOff, qkml + b * qkOff,
            1024, 1024, 1024, 4608,
            0, 0, 0, 0, 0, 0, 1, 2);

        // scores for batch b (8 heads)
        gemm_h3<<<dim3(2048 / 128, 2048 / 256, 8), 256, SMEM_3, st>>>(
            qkmh + b * qkOff, qkml + b * qkOff,
            qkmh + b * qkOff + 4096, qkml + b * qkOff + 4096,
            sc + b * scOff, nullptr, nullptr,
            512, 4608, 4608, 2048,
            0, 512, 0, 0, 0, 2048LL * 2048, 8, 0);

        // softmax for batch b
        softmax2048<<<8 * 2048, 256, 0, st>>>(sc + b * scOff, pr + b * scOff);

        // attn @ V for batch b
        cudaStreamWaitEvent(st, e3, 0);
        gemm_h1<<<dim3(1024 / 128, 2048 / 128, 8), 256, SMEM_1, st>>>(
            pr + b * scOff, vT + b * 2048, nullptr, ao + b * aoOff,
            2048, 2048, 4096, 8192,
            0, 2048LL * 2048, 0, 0, 0, 1024, 8, 1);

        // output projection for batch b
        gemm_h1<<<dim3(1024 / 128, 2048 / 128, 1), 256, SMEM_1, st>>>(
            ao + b * aoOff, Woh, out + b * outOff, nullptr,
            8192, 8192, 8192, 1024,
            0, 0, 0, 0, 0, 0, 1, 0);
    }

    // join batch-1 chain back to main stream
    cudaEventRecord(e4, s1);
    cudaStreamWaitEvent(0, e4, 0);
}

// round 17
// speedup vs baseline: 1.0095x; 1.0095x over previous
#include <cuda_runtime.h>
#include <cuda_fp16.h>
#include <math.h>
#include <stdint.h>

// ---------------------------------------------------------------------------
// GeometricAttentionLayer on GB300 — fp16 mma.sync + ldmatrix engine v6r2
//   R15 configuration (session best 1303.4us): term-major MMA ordering in
//   gemm_h3 with grouped fragment loads (ptxas schedules hoisting), 256x128
//   3-pass split GEMMs, 128x128 single-pass GEMMs, dual-stream batch pipeline.
// ---------------------------------------------------------------------------

#define BM 256
#define BN 128
#define BK 64
#define ATILE 32768                       // 256 rows x 128 B
#define BTILE 16384                       // 128 rows x 128 B
#define ST3 (2 * ATILE + 2 * BTILE)       // 96 KB / stage
#define SMEM_3 (2 * ST3)                  // 192 KB
#define ST1 (2 * BTILE)                   // 32 KB / stage (h1: 128x128)
#define SMEM_1 (3 * ST1)                  // 96 KB

__constant__ int c_ip[8] = {0, 2, 3, 4, 8, 9, 10, 14};

// ------------------------- scratch (device globals) ------------------------
__device__ __align__(1024) __half g_xh  [4096LL * 1024];
__device__ __align__(1024) __half g_xl  [4096LL * 1024];
__device__ __align__(1024) __half g_Wqkh[4608 * 1024];
__device__ __align__(1024) __half g_Wqkl[4608 * 1024];
__device__ __align__(1024) __half g_Wvh [1024 * 1024];
__device__ __align__(1024) __half g_Woh [1024 * 8192];
__device__ __align__(1024) __half g_qkmh[4096LL * 4608];
__device__ __align__(1024) __half g_qkml[4096LL * 4608];
__device__ __align__(1024) __half g_vT  [1024LL * 4096];
__device__ __align__(1024) float  g_sc  [16LL * 2048 * 2048];
__device__ __align__(1024) __half g_pr  [16LL * 2048 * 2048];
__device__ __align__(1024) __half g_ao  [4096LL * 8192];

// ------------------------------ helpers ------------------------------------
__device__ __forceinline__ uint32_t smem_u32(const void* p) {
    uint32_t a;
    asm("{ .reg .u64 t; cvta.to.shared.u64 t, %1; cvt.u32.u64 %0, t; }" : "=r"(a) : "l"(p));
    return a;
}

__device__ __forceinline__ void cp16(uint32_t dst, const __half* src) {
    asm volatile("cp.async.cg.shared.global [%0], [%1], 16;"
                 :: "r"(dst), "l"(src) : "memory");
}

#define LDSM_X4(r0, r1, r2, r3, addr)                                         \
    asm volatile("ldmatrix.sync.aligned.m8n8.x4.shared.b16 {%0,%1,%2,%3}, [%4];" \
        : "=r"(r0), "=r"(r1), "=r"(r2), "=r"(r3) : "r"(addr))

#define MMA_F16(acc, a, b)                                                    \
    asm volatile(                                                             \
        "mma.sync.aligned.m16n8k16.row.col.f32.f16.f16.f32 "                  \
        "{%0,%1,%2,%3}, {%4,%5,%6,%7}, {%8,%9}, {%0,%1,%2,%3};"               \
        : "+f"((acc)[0]), "+f"((acc)[1]), "+f"((acc)[2]), "+f"((acc)[3])      \
        : "r"((a)[0]), "r"((a)[1]), "r"((a)[2]), "r"((a)[3]),                 \
          "r"((b)[0]), "r"((b)[1]))

// ------------------- weight precompute (smem blade, 16 out/thread) ---------
__global__ __launch_bounds__(256) void make_weightT2(
    const float* __restrict__ w, const float* __restrict__ blade,
    __half* __restrict__ Wh, __half* __restrict__ Wl,
    int I, int mode, float scale, long long totalThreads, int storeLo)
{
    __shared__ float bl[9 * 256];
    for (int idx = threadIdx.x; idx < 9 * 256; idx += 256)
        bl[idx] = blade[idx];
    __syncthreads();

    long long t = (long long)blockIdx.x * 256 + threadIdx.x;
    if (t >= totalThreads) return;
    int col = (int)(t / I);
    int i   = (int)(t % I);

    int j, y;
    if (mode == 0)      { j = col >> 4; y = col & 15; }
    else if (mode == 1) { int e = col & 7; int d = (col >> 3) & 63; int h = col >> 9;
                          j = d * 8 + h; y = c_ip[e]; }
    else                { int e = col & 7; j = col >> 3; y = c_ip[e]; }

    float wr[9];
    const float* wp = w + ((long long)j * I + i) * 9;
    #pragma unroll
    for (int b = 0; b < 9; b++) wr[b] = wp[b];

    __half2 hv[8], lv[8];
    #pragma unroll
    for (int xc2 = 0; xc2 < 8; xc2++) {
        float s0 = 0.f, s1 = 0.f;
        #pragma unroll
        for (int b = 0; b < 9; b++) {
            s0 += wr[b] * bl[b * 256 + (xc2 * 2 + 0) * 16 + y];
            s1 += wr[b] * bl[b * 256 + (xc2 * 2 + 1) * 16 + y];
        }
        s0 *= scale; s1 *= scale;
        __half h0 = __float2half_rn(s0), h1 = __float2half_rn(s1);
        hv[xc2] = __halves2half2(h0, h1);
        lv[xc2] = __halves2half2(__float2half_rn(s0 - __half2float(h0)),
                                 __float2half_rn(s1 - __half2float(h1)));
    }

    long long base = (long long)col * (I * 16) + i * 16;
    __half2* oh = reinterpret_cast<__half2*>(Wh + base);
    #pragma unroll
    for (int u = 0; u < 8; u++) oh[u] = hv[u];
    if (storeLo) {
        __half2* ol = reinterpret_cast<__half2*>(Wl + base);
        #pragma unroll
        for (int u = 0; u < 8; u++) ol[u] = lv[u];
    }
}

// ------------------------------ fp16 split pass ----------------------------
__global__ void split_f16(const float4* __restrict__ in,
                          __half2* __restrict__ oh, __half2* __restrict__ ol, int n4)
{
    int i = blockIdx.x * 256 + threadIdx.x;
    if (i >= n4) return;
    float4 v = in[i];
    __half hx = __float2half_rn(v.x), hy = __float2half_rn(v.y);
    __half hz = __float2half_rn(v.z), hw = __float2half_rn(v.w);
    oh[i * 2 + 0] = __halves2half2(hx, hy);
    oh[i * 2 + 1] = __halves2half2(hz, hw);
    ol[i * 2 + 0] = __halves2half2(__float2half_rn(v.x - __half2float(hx)),
                                   __float2half_rn(v.y - __half2float(hy)));
    ol[i * 2 + 1] = __halves2half2(__float2half_rn(v.z - __half2float(hz)),
                                   __float2half_rn(v.w - __half2float(hw)));
}

// ------------------ single fp16 GEMM (NT), 128x128 tile --------------------
__global__ __launch_bounds__(256, 2) void gemm_h1(
    const __half* __restrict__ Ag, const __half* __restrict__ Bg,
    float* __restrict__ Cf, __half* __restrict__ Chh,
    int K, int lda, int ldb, int ldc,
    long long aB, long long aH, long long bB, long long bH,
    long long cB, long long cH, int nH, int halfout)
{
    extern __shared__ char sm[];
    const uint32_t smb = smem_u32(sm);

    const int tid = threadIdx.x;
    const int bb = blockIdx.z / nH, hh = blockIdx.z - bb * nH;
    const __half* A = Ag + bb * aB + hh * aH + (long long)(blockIdx.y * 128) * lda;
    const __half* B = Bg + bb * bB + hh * bH + (long long)(blockIdx.x * 128) * ldb;

    const int ldrow = tid >> 3;
    const int seg   = tid & 7;
    const uint32_t swoff = (uint32_t)((seg ^ (ldrow & 7)) << 4);
    uint32_t stoff[4];
    #pragma unroll
    for (int i = 0; i < 4; i++) stoff[i] = (uint32_t)((ldrow + 32 * i) * 128) + swoff;

#define ISSUE1(ch, slot) do {                                                 \
        const __half* _a = A + (long long)(ch) * BK + (seg << 3);             \
        uint32_t _da = smb + (uint32_t)(slot) * ST1;                          \
        _Pragma("unroll")                                                     \
        for (int _i = 0; _i < 4; _i++)                                        \
            cp16(_da + stoff[_i], _a + (long long)(ldrow + 32 * _i) * lda);   \
        const __half* _b = B + (long long)(ch) * BK + (seg << 3);             \
        uint32_t _db = smb + (uint32_t)(slot) * ST1 + BTILE;                  \
        _Pragma("unroll")                                                     \
        for (int _i = 0; _i < 4; _i++)                                        \
            cp16(_db + stoff[_i], _b + (long long)(ldrow + 32 * _i) * ldb);   \
    } while (0)

    const int lane = tid & 31;
    const int wm = ((tid >> 5) & 1) * 64;
    const int wn = (tid >> 6) * 32;
    const int qr = lane >> 2;
    const int qc = lane & 3;
    const int l7 = lane & 7;
    const uint32_t aRow = (uint32_t)(wm + (lane & 15)) * 128;
    const int aCb = lane >> 4;
    const uint32_t bRow = (uint32_t)(wn + l7 + ((lane >> 4) << 3)) * 128;
    const int bCb = (lane >> 3) & 1;

    float acc[4][4][4];
    #pragma unroll
    for (int mi = 0; mi < 4; mi++)
        #pragma unroll
        for (int ni = 0; ni < 4; ni++)
            #pragma unroll
            for (int q = 0; q < 4; q++) acc[mi][ni][q] = 0.f;

    const int nch = K >> 6;

    #pragma unroll
    for (int p = 0; p < 2; p++) {
        if (p < nch) ISSUE1(p, p);
        asm volatile("cp.async.commit_group;" ::: "memory");
    }

    for (int ch = 0; ch < nch; ch++) {
        asm volatile("cp.async.wait_group 1;" ::: "memory");
        __syncthreads();

        int pf = ch + 2;
        if (pf < nch) ISSUE1(pf, pf % 3);
        asm volatile("cp.async.commit_group;" ::: "memory");

        const int slot = ch % 3;
        const uint32_t tA = smb + slot * ST1 + aRow;
        const uint32_t tB = smb + slot * ST1 + BTILE + bRow;

        #pragma unroll
        for (int kk = 0; kk < 4; kk++) {
            const uint32_t aC = (uint32_t)((((kk << 1) + aCb) ^ l7) << 4);
            const uint32_t bC = (uint32_t)((((kk << 1) + bCb) ^ l7) << 4);
            uint32_t a[4][4], b[4][2];
            #pragma unroll
            for (int mi = 0; mi < 4; mi++)
                LDSM_X4(a[mi][0], a[mi][1], a[mi][2], a[mi][3], tA + mi * 2048 + aC);
            #pragma unroll
            for (int g = 0; g < 2; g++)
                LDSM_X4(b[2*g][0], b[2*g][1], b[2*g+1][0], b[2*g+1][1], tB + g * 2048 + bC);
            #pragma unroll
            for (int mi = 0; mi < 4; mi++)
                #pragma unroll
                for (int ni = 0; ni < 4; ni++)
                    MMA_F16(acc[mi][ni], a[mi], b[ni]);
        }
    }
#undef ISSUE1

    const long long cOff = bb * cB + hh * cH;
    const int rbase = blockIdx.y * 128 + wm + qr;
    const int cbase = blockIdx.x * 128 + wn + (qc << 1);
    #pragma unroll
    for (int mi = 0; mi < 4; mi++) {
        #pragma unroll
        for (int ni = 0; ni < 4; ni++) {
            const long long r = rbase + mi * 16;
            const int c = cbase + ni * 8;
            if (halfout) {
                __half* cb = Chh + cOff;
                *reinterpret_cast<__half2*>(&cb[r * ldc + c]) =
                    __halves2half2(__float2half_rn(acc[mi][ni][0]),
                                   __float2half_rn(acc[mi][ni][1]));
                *reinterpret_cast<__half2*>(&cb[(r + 8) * ldc + c]) =
                    __halves2half2(__float2half_rn(acc[mi][ni][2]),
                                   __float2half_rn(acc[mi][ni][3]));
            } else {
                float* cb = Cf + cOff;
                *reinterpret_cast<float2*>(&cb[r * ldc + c]) =
                    make_float2(acc[mi][ni][0], acc[mi][ni][1]);
                *reinterpret_cast<float2*>(&cb[(r + 8) * ldc + c]) =
                    make_float2(acc[mi][ni][2], acc[mi][ni][3]);
            }
        }
    }
}

// ------------------ 3-term fp16 split GEMM (NT), 256x128 tile --------------
// acc += Ahi*Bhi + Ahi*Blo + Alo*Bhi, issued term-major so consecutive MMAs
// hit independent accumulators (per-acc accumulation order unchanged).
__global__ __launch_bounds__(256, 1) void gemm_h3(
    const __half* __restrict__ Ah, const __half* __restrict__ Al,
    const __half* __restrict__ Bh, const __half* __restrict__ Bl,
    float* __restrict__ Cf, __half* __restrict__ Chh, __half* __restrict__ Chl,
    int K, int lda, int ldb, int ldc,
    long long aB, long long aH, long long bB, long long bH,
    long long cB, long long cH, int nH, int outmode)
{
    extern __shared__ char sm[];
    const uint32_t smb = smem_u32(sm);

    const int tid = threadIdx.x;
    const int bb = blockIdx.z / nH, hh = blockIdx.z - bb * nH;
    const long long aOff = bb * aB + hh * aH + (long long)(blockIdx.y * BM) * lda;
    const long long bOff = bb * bB + hh * bH + (long long)(blockIdx.x * BN) * ldb;
    const __half* pAh = Ah + aOff;
    const __half* pAl = Al + aOff;
    const __half* pBh = Bh + bOff;
    const __half* pBl = Bl + bOff;

    const int ldrow = tid >> 3;
    const int seg   = tid & 7;
    const uint32_t swoff = (uint32_t)((seg ^ (ldrow & 7)) << 4);

#define ISSUE3(ch, slot) do {                                                 \
        uint32_t _sb = smb + (uint32_t)(slot) * ST3;                          \
        const __half* _s0 = pAh + (long long)(ch) * BK + (seg << 3);          \
        const __half* _s1 = pAl + (long long)(ch) * BK + (seg << 3);          \
        _Pragma("unroll")                                                     \
        for (int _i = 0; _i < 8; _i++) {                                      \
            uint32_t _o = (uint32_t)((ldrow + 32 * _i) * 128) + swoff;        \
            long long _g = (long long)(ldrow + 32 * _i) * lda;                \
            cp16(_sb + _o, _s0 + _g);                                         \
            cp16(_sb + ATILE + _o, _s1 + _g);                                 \
        }                                                                     \
        const __half* _s2 = pBh + (long long)(ch) * BK + (seg << 3);          \
        const __half* _s3 = pBl + (long long)(ch) * BK + (seg << 3);          \
        _Pragma("unroll")                                                     \
        for (int _i = 0; _i < 4; _i++) {                                      \
            uint32_t _o = (uint32_t)((ldrow + 32 * _i) * 128) + swoff;        \
            long long _g = (long long)(ldrow + 32 * _i) * ldb;                \
            cp16(_sb + 2 * ATILE + _o, _s2 + _g);                             \
            cp16(_sb + 2 * ATILE + BTILE + _o, _s3 + _g);                     \
        }                                                                     \
    } while (0)

    const int lane = tid & 31;
    const int wid = tid >> 5;
    const int wm = (wid & 3) * 64;
    const int wn = (wid >> 2) * 64;
    const int qr = lane >> 2;
    const int qc = lane & 3;
    const int l7 = lane & 7;
    const uint32_t aRow = (uint32_t)(wm + (lane & 15)) * 128;
    const int aCb = lane >> 4;
    const uint32_t bRow = (uint32_t)(wn + l7 + ((lane >> 4) << 3)) * 128;
    const int bCb = (lane >> 3) & 1;

    float acc[4][8][4];
    #pragma unroll
    for (int mi = 0; mi < 4; mi++)
        #pragma unroll
        for (int ni = 0; ni < 8; ni++)
            #pragma unroll
            for (int q = 0; q < 4; q++) acc[mi][ni][q] = 0.f;

    const int nch = K >> 6;

    ISSUE3(0, 0);
    asm volatile("cp.async.commit_group;" ::: "memory");

    for (int ch = 0; ch < nch; ch++) {
        asm volatile("cp.async.wait_group 0;" ::: "memory");
        __syncthreads();
        if (ch + 1 < nch) {
            ISSUE3(ch + 1, (ch + 1) & 1);
            asm volatile("cp.async.commit_group;" ::: "memory");
        }

        const int slot = ch & 1;
        const uint32_t tAh = smb + slot * ST3 + aRow;
        const uint32_t tAl = smb + slot * ST3 + ATILE + aRow;
        const uint32_t tBh = smb + slot * ST3 + 2 * ATILE + bRow;
        const uint32_t tBl = smb + slot * ST3 + 2 * ATILE + BTILE + bRow;

        #pragma unroll
        for (int kk = 0; kk < 4; kk++) {
            const uint32_t aC = (uint32_t)((((kk << 1) + aCb) ^ l7) << 4);
            const uint32_t bC = (uint32_t)((((kk << 1) + bCb) ^ l7) << 4);
            uint32_t ah[4][4], al[4][4], bh[8][2], bl[8][2];
            #pragma unroll
            for (int mi = 0; mi < 4; mi++) {
                LDSM_X4(ah[mi][0], ah[mi][1], ah[mi][2], ah[mi][3], tAh + mi * 2048 + aC);
                LDSM_X4(al[mi][0], al[mi][1], al[mi][2], al[mi][3], tAl + mi * 2048 + aC);
            }
            #pragma unroll
            for (int g = 0; g < 4; g++) {
                LDSM_X4(bh[2*g][0], bh[2*g][1], bh[2*g+1][0], bh[2*g+1][1], tBh + g * 2048 + bC);
                LDSM_X4(bl[2*g][0], bl[2*g][1], bl[2*g+1][0], bl[2*g+1][1], tBl + g * 2048 + bC);
            }
            // term-major: consecutive MMAs on independent accumulators;
            // per-accumulator order remains ah*bl, al*bh, ah*bh.
            #pragma unroll
            for (int mi = 0; mi < 4; mi++)
                #pragma unroll
                for (int ni = 0; ni < 8; ni++)
                    MMA_F16(acc[mi][ni], ah[mi], bl[ni]);
            #pragma unroll
            for (int mi = 0; mi < 4; mi++)
                #pragma unroll
                for (int ni = 0; ni < 8; ni++)
                    MMA_F16(acc[mi][ni], al[mi], bh[ni]);
            #pragma unroll
            for (int mi = 0; mi < 4; mi++)
                #pragma unroll
                for (int ni = 0; ni < 8; ni++)
                    MMA_F16(acc[mi][ni], ah[mi], bh[ni]);
        }
    }
#undef ISSUE3

    const long long cOff = bb * cB + hh * cH;
    const int rbase = blockIdx.y * BM + wm + qr;
    const int cbase = blockIdx.x * BN + wn + (qc << 1);
    #pragma unroll
    for (int mi = 0; mi < 4; mi++) {
        #pragma unroll
        for (int ni = 0; ni < 8; ni++) {
            const long long r = rbase + mi * 16;
            const int c = cbase + ni * 8;
            float v[4] = {acc[mi][ni][0], acc[mi][ni][1], acc[mi][ni][2], acc[mi][ni][3]};
            if (outmode == 2) {
                __half h0 = __float2half_rn(v[0]), h1 = __float2half_rn(v[1]);
                __half h2 = __float2half_rn(v[2]), h3 = __float2half_rn(v[3]);
                __half* ch_ = Chh + cOff;
                __half* cl_ = Chl + cOff;
                *reinterpret_cast<__half2*>(&ch_[r * ldc + c])       = __halves2half2(h0, h1);
                *reinterpret_cast<__half2*>(&ch_[(r + 8) * ldc + c]) = __halves2half2(h2, h3);
                *reinterpret_cast<__half2*>(&cl_[r * ldc + c]) =
                    __halves2half2(__float2half_rn(v[0] - __half2float(h0)),
                                   __float2half_rn(v[1] - __half2float(h1)));
                *reinterpret_cast<__half2*>(&cl_[(r + 8) * ldc + c]) =
                    __halves2half2(__float2half_rn(v[2] - __half2float(h2)),
                                   __float2half_rn(v[3] - __half2float(h3)));
            } else {
                float* cb = Cf + cOff;
                __stcs(reinterpret_cast<float2*>(&cb[r * ldc + c]),
                       make_float2(v[0], v[1]));
                __stcs(reinterpret_cast<float2*>(&cb[(r + 8) * ldc + c]),
                       make_float2(v[2], v[3]));
            }
        }
    }
}

// ------------------------- softmax (2048 cols, fp32 -> half) ---------------
__global__ __launch_bounds__(256) void softmax2048(const float* __restrict__ sc,
                                                   __half* __restrict__ pr)
{
    __shared__ float red[8];
    const float4* p = reinterpret_cast<const float4*>(sc + (long long)blockIdx.x * 2048);
    __half2* q = reinterpret_cast<__half2*>(pr + (long long)blockIdx.x * 2048);
    const int t = threadIdx.x;
    const int wid = t >> 5, lid = t & 31;

    float4 a = __ldcs(p + t);
    float4 b = __ldcs(p + t + 256);

    float mx = fmaxf(fmaxf(fmaxf(a.x, a.y), fmaxf(a.z, a.w)),
                     fmaxf(fmaxf(b.x, b.y), fmaxf(b.z, b.w)));
    #pragma unroll
    for (int s = 16; s > 0; s >>= 1) mx = fmaxf(mx, __shfl_xor_sync(0xffffffffu, mx, s));
    if (lid == 0) red[wid] = mx;
    __syncthreads();
    if (t < 32) {
        float m = (t < 8) ? red[t] : -INFINITY;
        #pragma unroll
        for (int s = 4; s > 0; s >>= 1) m = fmaxf(m, __shfl_xor_sync(0xffffffffu, m, s));
        if (t == 0) red[0] = m;
    }
    __syncthreads();
    mx = red[0];
    __syncthreads();

    a.x = __expf(a.x - mx); a.y = __expf(a.y - mx); a.z = __expf(a.z - mx); a.w = __expf(a.w - mx);
    b.x = __expf(b.x - mx); b.y = __expf(b.y - mx); b.z = __expf(b.z - mx); b.w = __expf(b.w - mx);
    float sum = a.x + a.y + a.z + a.w + b.x + b.y + b.z + b.w;
    #pragma unroll
    for (int s = 16; s > 0; s >>= 1) sum += __shfl_xor_sync(0xffffffffu, sum, s);
    if (lid == 0) red[wid] = sum;
    __syncthreads();
    if (t < 32) {
        float m = (t < 8) ? red[t] : 0.f;
        #pragma unroll
        for (int s = 4; s > 0; s >>= 1) m += __shfl_xor_sync(0xffffffffu, m, s);
        if (t == 0) red[0] = m;
    }
    __syncthreads();
    float inv = 1.0f / red[0];

    __half2 q0 = __halves2half2(__float2half_rn(a.x * inv), __float2half_rn(a.y * inv));
    __half2 q1 = __halves2half2(__float2half_rn(a.z * inv), __float2half_rn(a.w * inv));
    __half2 q2 = __halves2half2(__float2half_rn(b.x * inv), __float2half_rn(b.y * inv));
    __half2 q3 = __halves2half2(__float2half_rn(b.z * inv), __float2half_rn(b.w * inv));
    uint2 u01 = make_uint2(*reinterpret_cast<uint32_t*>(&q0), *reinterpret_cast<uint32_t*>(&q1));
    uint2 u23 = make_uint2(*reinterpret_cast<uint32_t*>(&q2), *reinterpret_cast<uint32_t*>(&q3));
    __stcs(reinterpret_cast<uint2*>(q + t * 2), u01);
    __stcs(reinterpret_cast<uint2*>(q + (t + 256) * 2), u23);
}

// ------------------------------ host side ----------------------------------
template <typename T>
static T* sym_addr(const void* symbol)
{
    void* p = nullptr;
    cudaGetSymbolAddress(&p, symbol);
    return (T*)p;
}

extern "C" void kernel_launch(void* const* d_in, const int* in_sizes, int n_in,
                              void* d_out, int out_size)
{
    const float* x     = (const float*)d_in[0];
    const float* blade = (const float*)d_in[1];
    const float* w_q   = (const float*)d_in[2];
    const float* w_k   = (const float*)d_in[3];
    const float* w_v   = (const float*)d_in[4];
    const float* w_o   = (const float*)d_in[5];
    float* out = (float*)d_out;

    __half* xh   = sym_addr<__half>(g_xh),   *xl   = sym_addr<__half>(g_xl);
    __half* Wqkh = sym_addr<__half>(g_Wqkh), *Wqkl = sym_addr<__half>(g_Wqkl);
    __half* Wvh  = sym_addr<__half>(g_Wvh);
    __half* Woh  = sym_addr<__half>(g_Woh);
    __half* qkmh = sym_addr<__half>(g_qkmh), *qkml = sym_addr<__half>(g_qkml);
    __half* vT   = sym_addr<__half>(g_vT);
    float*  sc   = sym_addr<float >(g_sc);
    __half* pr   = sym_addr<__half>(g_pr);
    __half* ao   = sym_addr<__half>(g_ao);

    static cudaStream_t s1 = nullptr, s2 = nullptr;
    static cudaEvent_t eF = nullptr, e0 = nullptr, e1 = nullptr, e3 = nullptr, e4 = nullptr;
    if (s1 == nullptr) {
        cudaStreamCreateWithFlags(&s1, cudaStreamNonBlocking);
        cudaStreamCreateWithFlags(&s2, cudaStreamNonBlocking);
        cudaEventCreateWithFlags(&eF, cudaEventDisableTiming);
        cudaEventCreateWithFlags(&e0, cudaEventDisableTiming);
        cudaEventCreateWithFlags(&e1, cudaEventDisableTiming);
        cudaEventCreateWithFlags(&e3, cudaEventDisableTiming);
        cudaEventCreateWithFlags(&e4, cudaEventDisableTiming);
        cudaFuncSetAttribute(gemm_h1, cudaFuncAttributeMaxDynamicSharedMemorySize, SMEM_1);
        cudaFuncSetAttribute(gemm_h3, cudaFuncAttributeMaxDynamicSharedMemorySize, SMEM_3);
    }

    const float scale = 1.0f / sqrtf(512.0f);

    const long long xOff   = 2048LL * 1024;
    const long long qkOff  = 2048LL * 4608;
    const long long scOff  = 8LL * 2048 * 2048;
    const long long aoOff  = 2048LL * 8192;
    const long long outOff = 2048LL * 1024;

    // ---- fork ----
    cudaEventRecord(eF, 0);
    cudaStreamWaitEvent(s1, eF, 0);
    cudaStreamWaitEvent(s2, eF, 0);

    // s1: q+k weight precompute
    {
        long long tq = 4096LL * 64;
        make_weightT2<<<(unsigned)((tq + 255) / 256), 256, 0, s1>>>(
            w_q, blade, Wqkh, Wqkl, 64, 1, scale, tq, 1);
        long long tk = 512LL * 64;
        make_weightT2<<<(unsigned)((tk + 255) / 256), 256, 0, s1>>>(
            w_k, blade, Wqkh + 4096LL * 1024, Wqkl + 4096LL * 1024, 64, 2, 1.0f, tk, 1);
        cudaEventRecord(e1, s1);
    }
    // s2: v + o weight precompute
    {
        long long tv = 1024LL * 64;
        make_weightT2<<<(unsigned)((tv + 255) / 256), 256, 0, s2>>>(
            w_v, blade, Wvh, nullptr, 64, 0, 1.0f, tv, 0);
        long long to = 1024LL * 512;
        make_weightT2<<<(unsigned)((to + 255) / 256), 256, 0, s2>>>(
            w_o, blade, Woh, nullptr, 512, 0, 1.0f, to, 0);
    }

    // main: input split
    split_f16<<<4096, 256>>>((const float4*)x, (__half2*)xh, (__half2*)xl, 4096 * 1024 / 4);
    cudaEventRecord(e0, 0);

    // s2: v projection (all tokens): vT[f, m]
    cudaStreamWaitEvent(s2, e0, 0);
    gemm_h1<<<dim3(4096 / 128, 1024 / 128, 1), 256, SMEM_1, s2>>>(
        Wvh, xh, nullptr, vT, 1024, 1024, 1024, 4096,
        0, 0, 0, 0, 0, 0, 1, 1);
    cudaEventRecord(e3, s2);

    // ---- per-batch pipelines: batch 0 on stream 0, batch 1 on s1 ----
    cudaStreamWaitEvent(0, e1, 0);
    cudaStreamWaitEvent(s1, e0, 0);

    cudaStream_t bs[2] = { (cudaStream_t)0, s1 };
    for (int b = 0; b < 2; b++) {
        cudaStream_t st = bs[b];

        // qk projection (rows of batch b)
        gemm_h3<<<dim3(4608 / 128, 2048 / 256, 1), 256, SMEM_3, st>>>(
            xh + b * xOff, xl + b * xOff, Wqkh, Wqkl,
            nullptr, qkmh + b * qkOff, qkml + b * qkOff,
            1024, 1024, 1024, 4608,
            0, 0, 0, 0, 0, 0, 1, 2);

        // scores for batch b (8 heads)
        gemm_h3<<<dim3(2048 / 128, 2048 / 256, 8), 256, SMEM_3, st>>>(
            qkmh + b * qkOff, qkml + b * qkOff,
            qkmh + b * qkOff + 4096, qkml + b * qkOff + 4096,
            sc + b * scOff, nullptr, nullptr,
            512, 4608, 4608, 2048,
            0, 512, 0, 0, 0, 2048LL * 2048, 8, 0);

        // softmax for batch b
        softmax2048<<<8 * 2048, 256, 0, st>>>(sc + b * scOff, pr + b * scOff);

        // attn @ V for batch b
        cudaStreamWaitEvent(st, e3, 0);
        gemm_h1<<<dim3(1024 / 128, 2048 / 128, 8), 256, SMEM_1, st>>>(
            pr + b * scOff, vT + b * 2048, nullptr, ao + b * aoOff,
            2048, 2048, 4096, 8192,
            0, 2048LL * 2048, 0, 0, 0, 1024, 8, 1);

        // output projection for batch b
        gemm_h1<<<dim3(1024 / 128, 2048 / 128, 1), 256, SMEM_1, st>>>(
            ao + b * aoOff, Woh, out + b * outOff, nullptr,
            8192, 8192, 8192, 1024,
            0, 0, 0, 0, 0, 0, 1, 0);
    }

    // join batch-1 chain back to main stream
    cudaEventRecord(e4, s1);
    cudaStreamWaitEvent(0, e4, 0);
}